// round 4
// baseline (speedup 1.0000x reference)
#include <cuda_runtime.h>
#include <cuda_bf16.h>
#include <cstdint>

#define D_DIM   256
#define NPATCH  16384
#define VOCAB   4096

#define TILE_M  64
#define TILE_N  256
#define NT      16
#define KCH     8                      // 32-k chunks per N-tile
#define NSTEPS  (NT * KCH)             // 128

#define SMA_BYTES  (TILE_M * D_DIM * 2)   // 32768 (A resident, bf16)
#define SMB_STAGE  (TILE_N * 32 * 2)      // 16384 per stage
#define SMEM_BYTES (SMA_BYTES + 2 * SMB_STAGE)  // 65536

__device__ float         g_v2[VOCAB];
__device__ __nv_bfloat16 g_pb[NPATCH * D_DIM];
__device__ __nv_bfloat16 g_vb[VOCAB * D_DIM];

#define CP_ASYNC16(dst, src) \
    asm volatile("cp.async.cg.shared.global [%0], [%1], 16;" :: "r"((uint32_t)(dst)), "l"(src))
#define CP_COMMIT() asm volatile("cp.async.commit_group;" ::: "memory")

__device__ __forceinline__ void mma16(float* c, uint32_t a0, uint32_t a1, uint32_t a2, uint32_t a3,
                                      uint32_t b0, uint32_t b1) {
    asm("mma.sync.aligned.m16n8k16.row.col.f32.bf16.bf16.f32 "
        "{%0,%1,%2,%3}, {%4,%5,%6,%7}, {%8,%9}, {%0,%1,%2,%3};"
        : "+f"(c[0]), "+f"(c[1]), "+f"(c[2]), "+f"(c[3])
        : "r"(a0), "r"(a1), "r"(a2), "r"(a3), "r"(b0), "r"(b1));
}

// order-preserving float->uint key with idx packed in low 12 bits
__device__ __forceinline__ uint32_t fkey(float s, int n) {
    uint32_t b = __float_as_uint(s);
    uint32_t u = b ^ (uint32_t)(((int32_t)b >> 31) | 0x80000000);
    return (u & 0xFFFFF000u) | (uint32_t)n;
}
__device__ __forceinline__ float unkey(uint32_t key) {
    uint32_t u = key & 0xFFFFF000u;
    uint32_t b = (u & 0x80000000u) ? (u ^ 0x80000000u) : ~u;
    return __uint_as_float(b);
}

// within a 32-k block: lane t's 16B = [g0:{2t,2t+1,8+2t,8+2t+1}, g1:{same}]
__device__ __forceinline__ int perm32(int k) {
    return ((k & 7) >> 1) * 8 + ((k >> 4) & 1) * 4 + ((k >> 3) & 1) * 2 + (k & 1);
}

// ---------------------------------------------------------------------------
// prep kernels
// ---------------------------------------------------------------------------
__global__ void v2_kernel(const float* __restrict__ vocab, int V) {
    int v = blockIdx.x * 8 + (threadIdx.x >> 5);
    int lane = threadIdx.x & 31;
    if (v >= V) return;
    const float* row = vocab + v * D_DIM;
    float s = 0.f;
#pragma unroll
    for (int k = lane; k < D_DIM; k += 32) { float x = row[k]; s += x * x; }
#pragma unroll
    for (int o = 16; o > 0; o >>= 1) s += __shfl_down_sync(0xffffffffu, s, o);
    if (lane == 0) g_v2[v] = s;
}

__global__ void patchify_bf_kernel(const float* __restrict__ images,
                                   float* __restrict__ patches, int total) {
    int idx = blockIdx.x * blockDim.x + threadIdx.x;
    if (idx >= total) return;
    int d = idx & 255, n = (idx >> 8) & 255, b = idx >> 16;
    int ph = n >> 4, pw = n & 15, i = d >> 4, j = d & 15;
    float x = images[(b << 16) + ((ph * 16 + i) << 8) + pw * 16 + j];
    patches[idx] = x;
    g_pb[(idx & ~255) + (d & ~31) + perm32(d & 31)] = __float2bfloat16_rn(x);
}

__global__ void vocab_bf_kernel(const float* __restrict__ vocab, int total) {
    int idx = blockIdx.x * blockDim.x + threadIdx.x;
    if (idx >= total) return;
    int d = idx & 255;
    g_vb[(idx & ~255) + (d & ~31) + perm32(d & 31)] = __float2bfloat16_rn(vocab[idx]);
}

// ---------------------------------------------------------------------------
// bf16 mma coarse pass + best3 keys + exact fp32 rescue
// ---------------------------------------------------------------------------
__global__ __launch_bounds__(256, 2)
void vq_bf16_kernel(const float* __restrict__ patches,
                    const float* __restrict__ vocab,
                    float* __restrict__ tokens) {
    extern __shared__ char sm[];
    const uint32_t smem = (uint32_t)__cvta_generic_to_shared(sm);
    const uint32_t smA = smem;
    const uint32_t smB = smem + SMA_BYTES;

    const int tid  = threadIdx.x;
    const int lane = tid & 31;
    const int wid  = tid >> 5;
    const int g    = lane >> 2;
    const int t    = lane & 3;
    const int wm   = wid & 1;          // 2 m-warps (32 rows)
    const int wn   = wid >> 1;         // 4 n-warps (64 cols)
    const int p0   = blockIdx.x * TILE_M;

    // ---- prologue: A resident (swizzled), B stage 0 ----
    {
        const int r = tid >> 2, q = tid & 3;
#pragma unroll
        for (int uu = 0; uu < 8; uu++) {
            const int u = q * 8 + uu;                         // 16B unit 0..31
            CP_ASYNC16(smA + r * 512 + ((u ^ ((r & 7) << 2)) << 4),
                       g_pb + (p0 + r) * D_DIM + u * 8);
        }
        CP_COMMIT();
#pragma unroll
        for (int i = 0; i < 4; i++)
            CP_ASYNC16(smB + tid * 64 + i * 16, g_vb + tid * D_DIM + i * 8);
        CP_COMMIT();
    }

    uint32_t kb1[4], kb2[4], kb3[4];
#pragma unroll
    for (int i = 0; i < 4; i++) { kb1[i] = 0xFFFFFFFFu; kb2[i] = 0xFFFFFFFFu; kb3[i] = 0xFFFFFFFFu; }

#define BEST3(sl, kv) do { \
        uint32_t _k = (kv); \
        uint32_t _m1 = min(kb1[sl], _k), _x1 = max(kb1[sl], _k); kb1[sl] = _m1; \
        uint32_t _m2 = min(kb2[sl], _x1), _x2 = max(kb2[sl], _x1); kb2[sl] = _m2; \
        kb3[sl] = min(kb3[sl], _x2); \
    } while (0)

    int s = 0;
    for (int nt = 0; nt < NT; nt++) {
        float acc[2][8][4];
#pragma unroll
        for (int i = 0; i < 2; i++)
#pragma unroll
            for (int j = 0; j < 8; j++)
#pragma unroll
                for (int e = 0; e < 4; e++) acc[i][j][e] = 0.f;

#pragma unroll 1
        for (int kc = 0; kc < KCH; kc++, s++) {
            if (s + 1 < NSTEPS) {
                const int nt2 = (s + 1) >> 3, kc2 = (s + 1) & 7;
                const uint32_t dstB = smB + ((s + 1) & 1) * SMB_STAGE;
                const __nv_bfloat16* src = g_vb + (nt2 * TILE_N + tid) * D_DIM + kc2 * 32;
#pragma unroll
                for (int i = 0; i < 4; i++)
                    CP_ASYNC16(dstB + tid * 64 + i * 16, src + i * 8);
                CP_COMMIT();
                asm volatile("cp.async.wait_group 1;" ::: "memory");
            } else {
                asm volatile("cp.async.wait_group 0;" ::: "memory");
            }
            __syncthreads();

            // A fragments: one uint4 per (m-tile, row-half) covers both 16-k groups
            uint4 af[2][2];
            const uint32_t aoff = (uint32_t)(((kc ^ g) << 6) | (t << 4));
#pragma unroll
            for (int i = 0; i < 2; i++)
#pragma unroll
                for (int h = 0; h < 2; h++)
                    af[i][h] = *(const uint4*)(sm + (wm * 32 + i * 16 + h * 8 + g) * 512 + aoff);

            const char* Bb = sm + SMA_BYTES + (s & 1) * SMB_STAGE;
#pragma unroll
            for (int jh = 0; jh < 2; jh++) {
                uint4 bf[4];
#pragma unroll
                for (int jj = 0; jj < 4; jj++) {
                    const int n = wn * 64 + (jh * 4 + jj) * 8 + g;
                    bf[jj] = *(const uint4*)(Bb + n * 64 + t * 16);
                }
#pragma unroll
                for (int i = 0; i < 2; i++)
#pragma unroll
                    for (int jj = 0; jj < 4; jj++) {
                        float* c = acc[i][jh * 4 + jj];
                        mma16(c, af[i][0].x, af[i][1].x, af[i][0].y, af[i][1].y, bf[jj].x, bf[jj].y);
                        mma16(c, af[i][0].z, af[i][1].z, af[i][0].w, af[i][1].w, bf[jj].z, bf[jj].w);
                    }
            }
            __syncthreads();
        }

        // running best3 per owned row-slot
#pragma unroll
        for (int j = 0; j < 8; j++) {
            const int n0 = nt * TILE_N + wn * 64 + j * 8 + 2 * t;
            const float2 vv = __ldg((const float2*)(g_v2 + n0));
#pragma unroll
            for (int i = 0; i < 2; i++) {
                BEST3(i * 2 + 0, fkey(vv.x - 2.f * acc[i][j][0], n0));
                BEST3(i * 2 + 0, fkey(vv.y - 2.f * acc[i][j][1], n0 + 1));
                BEST3(i * 2 + 1, fkey(vv.x - 2.f * acc[i][j][2], n0));
                BEST3(i * 2 + 1, fkey(vv.y - 2.f * acc[i][j][3], n0 + 1));
            }
        }
    }

    // ---- dump candidates (reuse B region) ----
    __syncthreads();
    uint4* cand = (uint4*)(sm + SMA_BYTES);   // [64 rows][16 slots]
#pragma unroll
    for (int i = 0; i < 2; i++)
#pragma unroll
        for (int h = 0; h < 2; h++) {
            const int r = wm * 32 + i * 16 + h * 8 + g;
            const int sl = i * 2 + h;
            cand[r * 16 + wn * 4 + t] = make_uint4(kb1[sl], kb2[sl], kb3[sl], 0u);
        }
    __syncthreads();

    // ---- exact fp32 rescue ----
    if (tid < TILE_M) {
        const int r = tid;
        float m = 3.4e38f;
#pragma unroll 1
        for (int sl = 0; sl < 16; sl++) {
            const uint4 c = cand[r * 16 + sl];
            m = fminf(m, unkey(c.x));
            m = fminf(m, unkey(c.y));
            m = fminf(m, unkey(c.z));
        }
        const float thr = m + 2.5f;
        float bestv = 3.4e38f;
        int   besti = 0x7FFFFFFF;
        const float* pp = patches + (size_t)(p0 + r) * D_DIM;
#pragma unroll 1
        for (int sl = 0; sl < 16; sl++) {
            const uint4 c = cand[r * 16 + sl];
            const uint32_t ks[3] = {c.x, c.y, c.z};
#pragma unroll
            for (int e = 0; e < 3; e++) {
                if (unkey(ks[e]) <= thr) {
                    const int vi = (int)(ks[e] & 0xFFFu);
                    const float* vp = vocab + (size_t)vi * D_DIM;
                    float dot = 0.f;
#pragma unroll 8
                    for (int k4 = 0; k4 < 64; k4++) {
                        const float4 a = *(const float4*)(pp + k4 * 4);
                        const float4 b = *(const float4*)(vp + k4 * 4);
                        dot += a.x * b.x; dot += a.y * b.y;
                        dot += a.z * b.z; dot += a.w * b.w;
                    }
                    const float se = __ldg(&g_v2[vi]) - 2.f * dot;
                    if (se < bestv || (se == bestv && vi < besti)) { bestv = se; besti = vi; }
                }
            }
        }
        tokens[p0 + r] = (float)besti;
    }
}

// ---------------------------------------------------------------------------
extern "C" void kernel_launch(void* const* d_in, const int* in_sizes, int n_in,
                              void* d_out, int out_size) {
    const float* images = (const float*)d_in[0];   // [64, 256, 256]
    const float* vocab  = (const float*)d_in[1];   // [4096, 256]
    float* out = (float*)d_out;

    const int npix = in_sizes[0];                  // 4194304
    const int nvoc = in_sizes[1];                  // 1048576
    const int V  = nvoc / D_DIM;                   // 4096
    const int NP = npix / D_DIM;                   // 16384

    float* patches = out;
    float* tokens  = out + npix;

    v2_kernel<<<(V + 7) / 8, 256>>>(vocab, V);
    vocab_bf_kernel<<<(nvoc + 255) / 256, 256>>>(vocab, nvoc);
    patchify_bf_kernel<<<(npix + 255) / 256, 256>>>(images, patches, npix);

    cudaFuncSetAttribute(vq_bf16_kernel, cudaFuncAttributeMaxDynamicSharedMemorySize, SMEM_BYTES);
    vq_bf16_kernel<<<NP / TILE_M, 256, SMEM_BYTES>>>(patches, vocab, tokens);
}